// round 5
// baseline (speedup 1.0000x reference)
#include <cuda_runtime.h>
#include <cstdint>
#include <math.h>

#define B  16
#define H  512
#define V  32000
#define NL 2

// ---------------- device state (no allocs allowed) ----------------
// h ping-pong per layer: [layer][ping][b][h]. c has no cross-thread hazard.
__device__ float g_hbuf[NL][2][B][H];
__device__ float g_c[NL][B][H];
__device__ unsigned long long g_amax[B];

// ---------------- f32x2 packed helpers ----------------
__device__ __forceinline__ unsigned long long fma2(unsigned long long a,
                                                   unsigned long long b,
                                                   unsigned long long c) {
    unsigned long long d;
    asm("fma.rn.f32x2 %0,%1,%2,%3;" : "=l"(d) : "l"(a), "l"(b), "l"(c));
    return d;
}
__device__ __forceinline__ float2 unpk(unsigned long long a) {
    float2 r;
    asm("mov.b64 {%0,%1},%2;" : "=f"(r.x), "=f"(r.y) : "l"(a));
    return r;
}

// ---------------- init: zero state ----------------
__global__ void init_kernel() {
    int tid = blockIdx.x * blockDim.x + threadIdx.x;
    int stride = gridDim.x * blockDim.x;
    float* p = &g_hbuf[0][0][0][0];
    for (int i = tid; i < NL * 2 * B * H; i += stride) p[i] = 0.f;
    float* q = &g_c[0][0][0];
    for (int i = tid; i < NL * B * H; i += stride) q[i] = 0.f;
    if (blockIdx.x == 0 && threadIdx.x < B) g_amax[threadIdx.x] = 0ull;
}

// ---------------- LSTM cell kernel ----------------
// grid (64, 2): x = j-group (8 j each), y = b-group (8 b each). 256 threads:
// tid -> gate (4) x b_local (8) x j_local (8). Each thread computes one gate
// pre-activation = dot(inp,Wih_row) + dot(h,Whh_row) with f32x2 k-pairs.
// mode: 0 = input is x, 1 = input is W_tied[argmax], 2 = input is h of layer0.
__global__ __launch_bounds__(256) void lstm_kernel(
    const float* __restrict__ Wih, const float* __restrict__ Whh,
    const float* __restrict__ bih, const float* __restrict__ bhh,
    const float* __restrict__ x,   const float* __restrict__ Wt,
    int mode, int layer, int ping, int do_reset)
{
    __shared__ __align__(16) float s_in[8][H];
    __shared__ __align__(16) float s_h[8][H];
    __shared__ float s_g[4][8][8];

    const int tid = threadIdx.x;
    const int jg = blockIdx.x;   // 0..63
    const int bg = blockIdx.y;   // 0..1

    // reset argmax accumulator for THIS step's logits kernel (mode 2 never
    // reads g_amax, and the mode-1 consumer ran in the previous kernel).
    if (do_reset && jg == 0 && bg == 0 && tid < B) g_amax[tid] = 0ull;

    // cooperative stage of the 8 input rows + 8 h rows for this b-group
    for (int i = tid; i < 8 * (H / 4); i += 256) {
        int r = i >> 7;          // 0..7
        int col = i & 127;       // float4 column
        int b = bg * 8 + r;
        const float* rowp;
        if (mode == 0) {
            rowp = x + (size_t)b * H;
        } else if (mode == 1) {
            unsigned idx = ~(unsigned)(g_amax[b]);   // stored as ~v
            rowp = Wt + (size_t)idx * H;
        } else {
            rowp = &g_hbuf[0][1 - ping][b][0];       // layer0's NEW h
        }
        *(float4*)&s_in[r][col * 4] = *(const float4*)(rowp + col * 4);
        const float* hp = &g_hbuf[layer][ping][b][0];
        *(float4*)&s_h[r][col * 4] = *(const float4*)(hp + col * 4);
    }
    __syncthreads();

    const int gate = tid >> 6;
    const int rem  = tid & 63;
    const int bl   = rem >> 3;
    const int jl   = rem & 7;
    const int j    = jg * 8 + jl;
    const int row  = gate * H + j;

    const ulonglong2* wi = (const ulonglong2*)(Wih + (size_t)row * H);
    const ulonglong2* wh = (const ulonglong2*)(Whh + (size_t)row * H);
    const ulonglong2* si = (const ulonglong2*)&s_in[bl][0];
    const ulonglong2* sh = (const ulonglong2*)&s_h[bl][0];

    unsigned long long a0 = 0, a1 = 0, c0 = 0, c1 = 0;
#pragma unroll 4
    for (int kk = 0; kk < H / 4; kk++) {
        ulonglong2 w1 = wi[kk]; ulonglong2 i1 = si[kk];
        a0 = fma2(w1.x, i1.x, a0);
        a1 = fma2(w1.y, i1.y, a1);
        ulonglong2 w2 = wh[kk]; ulonglong2 h1 = sh[kk];
        c0 = fma2(w2.x, h1.x, c0);
        c1 = fma2(w2.y, h1.y, c1);
    }
    float2 fa0 = unpk(a0), fa1 = unpk(a1), fb0 = unpk(c0), fb1 = unpk(c1);
    float g = fa0.x + fa0.y + fa1.x + fa1.y + fb0.x + fb0.y + fb1.x + fb1.y
            + bih[row] + bhh[row];
    s_g[gate][bl][jl] = g;
    __syncthreads();

    if (tid < 64) {
        int bl2 = tid >> 3, jl2 = tid & 7;
        int b  = bg * 8 + bl2;
        int j2 = jg * 8 + jl2;
        float gi = s_g[0][bl2][jl2];
        float gf = s_g[1][bl2][jl2];
        float gg = s_g[2][bl2][jl2];
        float go = s_g[3][bl2][jl2];
        float c_old = g_c[layer][b][j2];
        float si_ = 1.f / (1.f + expf(-gi));
        float sf  = 1.f / (1.f + expf(-gf));
        float so  = 1.f / (1.f + expf(-go));
        float cn = sf * c_old + si_ * tanhf(gg);
        float hn = so * tanhf(cn);
        g_c[layer][b][j2] = cn;
        g_hbuf[layer][1 - ping][b][j2] = hn;
    }
}

// ---------------- logits + argmax kernel ----------------
// 250 blocks x 128 threads, one vocab row per thread. h1 staged in smem,
// 16 f32x2 accumulators (one per batch), W row streamed as ulonglong2.
__global__ __launch_bounds__(128) void logits_kernel(
    const float* __restrict__ Wt, const float* __restrict__ bp,
    float* __restrict__ out, int t, int T, int ping)
{
    __shared__ __align__(16) float s_h[B][H];          // 32 KB
    __shared__ unsigned long long s_best[B][4];

    const int tid = threadIdx.x;
    const float* hp = &g_hbuf[1][1 - ping][0][0];
    for (int i = tid; i < B * H / 4; i += 128)
        ((float4*)&s_h[0][0])[i] = ((const float4*)hp)[i];
    __syncthreads();

    const int v = blockIdx.x * 128 + tid;              // exactly covers 32000

    unsigned long long acc[B];
#pragma unroll
    for (int b = 0; b < B; b++) acc[b] = 0ull;

    const ulonglong2* w = (const ulonglong2*)(Wt + (size_t)v * H);
#pragma unroll 2
    for (int kk = 0; kk < H / 4; kk++) {
        ulonglong2 wv = w[kk];
#pragma unroll
        for (int b = 0; b < B; b++) {
            ulonglong2 hv = ((const ulonglong2*)&s_h[b][0])[kk];
            acc[b] = fma2(wv.x, hv.x, acc[b]);
            acc[b] = fma2(wv.y, hv.y, acc[b]);
        }
    }

    const float bias = bp[v];
    const int lane = tid & 31, wrp = tid >> 5;
#pragma unroll
    for (int b = 0; b < B; b++) {
        float2 f = unpk(acc[b]);
        float logit = f.x + f.y + bias;
        out[((size_t)b * T + t) * (size_t)V + v] = logit;

        // order-preserving encode; tie-break -> lowest v (matches jnp.argmax)
        unsigned ub = __float_as_uint(logit);
        ub = (ub & 0x80000000u) ? ~ub : (ub | 0x80000000u);
        unsigned long long p = ((unsigned long long)ub << 32) | (unsigned)(~v);
#pragma unroll
        for (int off = 16; off; off >>= 1) {
            unsigned long long q = __shfl_xor_sync(0xffffffffu, p, off);
            if (q > p) p = q;
        }
        if (lane == 0) s_best[b][wrp] = p;
    }
    __syncthreads();
    if (tid < B) {
        unsigned long long p = s_best[tid][0];
#pragma unroll
        for (int wi = 1; wi < 4; wi++) {
            unsigned long long q = s_best[tid][wi];
            if (q > p) p = q;
        }
        atomicMax(&g_amax[tid], p);
    }
}

// ---------------- launch ----------------
extern "C" void kernel_launch(void* const* d_in, const int* in_sizes, int n_in,
                              void* d_out, int out_size) {
    const float* x   = (const float*)d_in[0];
    const float* Wt  = (const float*)d_in[1];
    const float* bp  = (const float*)d_in[2];
    const float* Wih = (const float*)d_in[3];   // [L][4H][H]
    const float* Whh = (const float*)d_in[4];
    const float* bih = (const float*)d_in[5];   // [L][4H]
    const float* bhh = (const float*)d_in[6];
    float* out = (float*)d_out;

    const int T = out_size / (B * V);
    if (T <= 0) return;

    init_kernel<<<32, 256>>>();

    dim3 lgrid(64, 2);
    for (int t = 0; t < T; t++) {
        int ping = t & 1;
        // layer 0: input = x (t==0) or W_tied[argmax(prev logits)]
        lstm_kernel<<<lgrid, 256>>>(Wih, Whh, bih, bhh, x, Wt,
                                    (t == 0 ? 0 : 1), 0, ping, 0);
        // layer 1: input = layer0's new h; also resets g_amax for this step
        lstm_kernel<<<lgrid, 256>>>(Wih + 4 * H * H, Whh + 4 * H * H,
                                    bih + 4 * H, bhh + 4 * H, x, Wt,
                                    2, 1, ping, 1);
        // logits + stream write + argmax
        logits_kernel<<<250, 128>>>(Wt, bp, out, t, T, ping);
    }
}

// round 10
// speedup vs baseline: 1.7744x; 1.7744x over previous
#include <cuda_runtime.h>
#include <cstdint>
#include <math.h>

#define B   16
#define H   512
#define V   32000
#define NL  2
#define NBLK 148          // one full wave, all co-resident (GB300 has 152 SMs)
#define NLSTM_BLK 128     // blocks doing LSTM work
#define NLOGIT_BLK 125    // 125*256 = 32000 = V

typedef unsigned long long u64;

// ---------------- device state ----------------
__device__ float g_h[2][NL][B][H];     // ping-pong hidden state
__device__ u64 g_amax[2][B];           // double-buffered argmax accumulator
__device__ unsigned g_cnt;             // monotonic barrier counter

// ---------------- packed f32x2 helpers ----------------
__device__ __forceinline__ u64 fma2(u64 a, u64 b, u64 c) {
    u64 d; asm("fma.rn.f32x2 %0,%1,%2,%3;" : "=l"(d) : "l"(a), "l"(b), "l"(c));
    return d;
}
__device__ __forceinline__ u64 add2(u64 a, u64 b) {
    u64 d; asm("add.rn.f32x2 %0,%1,%2;" : "=l"(d) : "l"(a), "l"(b));
    return d;
}
__device__ __forceinline__ float2 unpk(u64 a) {
    float2 r; asm("mov.b64 {%0,%1},%2;" : "=f"(r.x), "=f"(r.y) : "l"(a));
    return r;
}
__device__ __forceinline__ float sigm(float x) { return 1.f / (1.f + expf(-x)); }

// ---------------- grid barrier: monotonic counter, release-add / acquire-spin
// Every arrive is red.release; the spin is ld.acquire on the SAME address, so
// an acquire-load observing cnt >= NBLK*target synchronizes-with every block's
// release-arrive -> full cumulative visibility of their prior writes. No
// releaser role, no reset, no cross-address relaxed-atomic ordering assumed.
__device__ __forceinline__ void gbar(unsigned target) {
    __syncthreads();
    if (threadIdx.x == 0) {
        asm volatile("red.release.gpu.global.add.u32 [%0], 1;"
                     :: "l"(&g_cnt) : "memory");
        const unsigned need = NBLK * target;
        unsigned v;
        do {
            asm volatile("ld.acquire.gpu.global.u32 %0, [%1];"
                         : "=r"(v) : "l"(&g_cnt) : "memory");
        } while (v < need);
    }
    __syncthreads();
}

// ---------------- init ----------------
__global__ void init_kernel() {
    int tid = blockIdx.x * blockDim.x + threadIdx.x;
    int stride = gridDim.x * blockDim.x;
    float* p = &g_h[0][0][0][0];
    for (int i = tid; i < 2 * NL * B * H; i += stride) p[i] = 0.f;
    if (blockIdx.x == 0 && threadIdx.x < 2 * B)
        (&g_amax[0][0])[threadIdx.x] = 0ull;
    if (blockIdx.x == 0 && threadIdx.x == 0) g_cnt = 0u;
}

// ---------------- persistent decoder ----------------
__global__ __launch_bounds__(256) void decoder_kernel(
    const float* __restrict__ x,   const float* __restrict__ Wt,
    const float* __restrict__ bp,  const float* __restrict__ Wih,
    const float* __restrict__ Whh, const float* __restrict__ bih,
    const float* __restrict__ bhh, float* __restrict__ out, int T)
{
    __shared__ __align__(16) float s_mem[8192];   // 32 KB: LSTM {in,h} or logits h16
    __shared__ float s_g[8][4][8];                // per-warp gate sums
    __shared__ u64 s_best[B][8];

    const int tid  = threadIdx.x;
    const int bx   = blockIdx.x;
    const int lane = tid & 31;
    const int warp = tid >> 5;

    // LSTM role: warp <-> (j, b-half); lane <-> K-chunk of concat K=1024
    const int bbase = (bx & 1) * 8;
    const int j     = (bx >> 1) * 8 + warp;      // 0..511 (used only when bx<128)
    const int kside = lane >> 4;                 // 0: Wih*in, 1: Whh*h
    const int k0    = (lane & 15) * 32;          // float offset within row

    float c_reg[2] = {0.f, 0.f};                 // cell state lives in registers
    unsigned target = 0;

#pragma unroll 1
    for (int t = 0; t < T; t++) {
        const int p = t & 1;                     // h read side; write side = 1-p
        // amax slots: step t-1 logits wrote slot 1-p; step t logits writes
        // slot p and resets slot 1-p for step t+1.

        // ================= LSTM layers =================
#pragma unroll
        for (int layer = 0; layer < NL; layer++) {
            if (bx < NLSTM_BLK) {
                float* s_in = s_mem;             // [8][512]
                float* s_h  = s_mem + 4096;      // [8][512]
                // ---- stage input + recurrent h (8 batches of this half) ----
                for (int i = tid; i < 1024; i += 256) {
                    int r = i >> 7, c4 = i & 127;
                    int b = bbase + r;
                    const float4* srcp;
                    if (layer == 0) {
                        if (t == 0) {
                            srcp = (const float4*)(x + (size_t)b * H) + c4;
                        } else {
                            u64 am;
                            asm volatile("ld.global.cg.u64 %0,[%1];"
                                         : "=l"(am) : "l"(&g_amax[1 - p][b])
                                         : "memory");
                            unsigned idx = ~(unsigned)am;
                            if (idx >= V) idx = 0;   // defensive: never OOB
                            srcp = (const float4*)(Wt + (size_t)idx * H) + c4;
                        }
                    } else {
                        srcp = (const float4*)(&g_h[1 - p][0][b][0]) + c4;
                    }
                    ((float4*)s_in)[(r << 7) + c4] = __ldcg(srcp);
                    ((float4*)s_h)[(r << 7) + c4] =
                        __ldcg((const float4*)(&g_h[p][layer][b][0]) + c4);
                }
                __syncthreads();

                // ---- partial dot: 4 gate rows x 8 batches, K-chunk of 32 ----
                const float* Wsel = (kside ? Whh : Wih) + (size_t)layer * 4 * H * H;
                const float* ssel = kside ? s_h : s_in;
                const ulonglong2* wr0 = (const ulonglong2*)(Wsel + (size_t)(0 * H + j) * H + k0);
                const ulonglong2* wr1 = (const ulonglong2*)(Wsel + (size_t)(1 * H + j) * H + k0);
                const ulonglong2* wr2 = (const ulonglong2*)(Wsel + (size_t)(2 * H + j) * H + k0);
                const ulonglong2* wr3 = (const ulonglong2*)(Wsel + (size_t)(3 * H + j) * H + k0);

                u64 acc[4][8];
#pragma unroll
                for (int g = 0; g < 4; g++)
#pragma unroll
                    for (int b8 = 0; b8 < 8; b8++) acc[g][b8] = 0ull;

#pragma unroll
                for (int kk = 0; kk < 8; kk++) {
                    ulonglong2 w0 = wr0[kk], w1 = wr1[kk], w2 = wr2[kk], w3 = wr3[kk];
#pragma unroll
                    for (int b8 = 0; b8 < 8; b8++) {
                        ulonglong2 sv = ((const ulonglong2*)(ssel + (b8 << 9) + k0))[kk];
                        acc[0][b8] = fma2(w0.x, sv.x, acc[0][b8]);
                        acc[0][b8] = fma2(w0.y, sv.y, acc[0][b8]);
                        acc[1][b8] = fma2(w1.x, sv.x, acc[1][b8]);
                        acc[1][b8] = fma2(w1.y, sv.y, acc[1][b8]);
                        acc[2][b8] = fma2(w2.x, sv.x, acc[2][b8]);
                        acc[2][b8] = fma2(w2.y, sv.y, acc[2][b8]);
                        acc[3][b8] = fma2(w3.x, sv.x, acc[3][b8]);
                        acc[3][b8] = fma2(w3.y, sv.y, acc[3][b8]);
                    }
                }
                // ---- warp tree-reduce over the 32 K-chunks (result -> lane 0) ----
#pragma unroll
                for (int off = 16; off >= 1; off >>= 1) {
#pragma unroll
                    for (int g = 0; g < 4; g++)
#pragma unroll
                        for (int b8 = 0; b8 < 8; b8++)
                            acc[g][b8] = add2(acc[g][b8],
                                __shfl_down_sync(0xffffffffu, acc[g][b8], off));
                }
                if (lane == 0) {
#pragma unroll
                    for (int g = 0; g < 4; g++)
#pragma unroll
                        for (int b8 = 0; b8 < 8; b8++) {
                            float2 f = unpk(acc[g][b8]);
                            s_g[warp][g][b8] = f.x + f.y;
                        }
                }
                __syncwarp();
                // ---- activations: lane b8 owns cell (layer, bbase+b8, j) ----
                if (lane < 8) {
                    int b = bbase + lane;
                    const float* bi = bih + (size_t)layer * 4 * H;
                    const float* bh = bhh + (size_t)layer * 4 * H;
                    float gi = s_g[warp][0][lane] + bi[0 * H + j] + bh[0 * H + j];
                    float gf = s_g[warp][1][lane] + bi[1 * H + j] + bh[1 * H + j];
                    float gg = s_g[warp][2][lane] + bi[2 * H + j] + bh[2 * H + j];
                    float go = s_g[warp][3][lane] + bi[3 * H + j] + bh[3 * H + j];
                    float cn = sigm(gf) * c_reg[layer] + sigm(gi) * tanhf(gg);
                    float hn = sigm(go) * tanhf(cn);
                    c_reg[layer] = cn;
                    g_h[1 - p][layer][b][j] = hn;
                }
            }
            gbar(++target);
        }

        // ================= logits + argmax =================
        if (bx < NLOGIT_BLK) {
            // reset the OTHER slot for step t+1 (nothing touches it until then)
            if (bx == 0 && tid < B) atomicExch(&g_amax[1 - p][tid], 0ull);

            // stage h1 [16][512] into smem
            const float4* hp = (const float4*)(&g_h[1 - p][1][0][0]);
            for (int i = tid; i < 2048; i += 256)
                ((float4*)s_mem)[i] = __ldcg(hp + i);
            __syncthreads();

            const int v = bx * 256 + tid;
            const ulonglong2* wrow = (const ulonglong2*)(Wt + (size_t)v * H);
            u64 acc[B];
#pragma unroll
            for (int b = 0; b < B; b++) acc[b] = 0ull;

#pragma unroll 4
            for (int kk = 0; kk < H / 4; kk++) {
                ulonglong2 wv = wrow[kk];
#pragma unroll
                for (int b = 0; b < B; b++) {
                    ulonglong2 hv = ((const ulonglong2*)(s_mem + (b << 9)))[kk];
                    acc[b] = fma2(wv.x, hv.x, acc[b]);
                    acc[b] = fma2(wv.y, hv.y, acc[b]);
                }
            }

            const float bias = bp[v];
#pragma unroll
            for (int b = 0; b < B; b++) {
                float2 f = unpk(acc[b]);
                float logit = f.x + f.y + bias;
                __stcs(&out[((size_t)b * T + t) * (size_t)V + v], logit);

                // order-preserving encode; tie-break -> lowest v (jnp.argmax)
                unsigned ub = __float_as_uint(logit);
                ub = (ub & 0x80000000u) ? ~ub : (ub | 0x80000000u);
                u64 pk = ((u64)ub << 32) | (unsigned)(~v);
#pragma unroll
                for (int off = 16; off; off >>= 1) {
                    u64 q = __shfl_xor_sync(0xffffffffu, pk, off);
                    if (q > pk) pk = q;
                }
                if (lane == 0) s_best[b][warp] = pk;
            }
            __syncthreads();
            if (tid < B) {
                u64 pk = s_best[tid][0];
#pragma unroll
                for (int w = 1; w < 8; w++) {
                    u64 q = s_best[tid][w];
                    if (q > pk) pk = q;
                }
                atomicMax(&g_amax[p][tid], pk);
            }
        }
        gbar(++target);
    }
}

// ---------------- launch ----------------
extern "C" void kernel_launch(void* const* d_in, const int* in_sizes, int n_in,
                              void* d_out, int out_size) {
    const float* x   = (const float*)d_in[0];
    const float* Wt  = (const float*)d_in[1];
    const float* bp  = (const float*)d_in[2];
    const float* Wih = (const float*)d_in[3];
    const float* Whh = (const float*)d_in[4];
    const float* bih = (const float*)d_in[5];
    const float* bhh = (const float*)d_in[6];
    float* out = (float*)d_out;

    const int T = out_size / (B * V);
    if (T <= 0) return;

    init_kernel<<<32, 256>>>();
    decoder_kernel<<<NBLK, 256>>>(x, Wt, bp, Wih, Whh, bih, bhh, out, T);
}